// round 17
// baseline (speedup 1.0000x reference)
#include <cuda_runtime.h>
#include <cuda_fp16.h>
#include <cstdint>
#include <cstddef>

#define Hd 128
#define FEAT 512
#define NSRC0 50000
#define NDST0 20000
#define NDST1 4096
#define E0 320000
#define E1 65536

#define OFF_S0 0
#define OFF_D0 (NSRC0)
#define OFF_S1 (NSRC0 + NDST0)
#define OFF_D1 (NSRC0 + 2 * NDST0)
#define CNT_TOTAL (NSRC0 + 2 * NDST0 + NDST1)

// ---------------- scratch (device globals; no allocations) ----------------
__device__ __half g_Xh[(size_t)NSRC0 * FEAT];     // fp16 node-major src features
__device__ __half g_agg0[(size_t)NDST0 * FEAT];   // fp16 aggregated layer-0 input
__device__ __half g_h0[(size_t)NDST0 * FEAT];     // fp16 layer-0 output * ns1

__device__ int g_cnt[CNT_TOTAL];
__device__ float g_ns0[NSRC0];
__device__ float g_nd0[NDST0];
__device__ float g_ns1[NDST0];
__device__ float g_nd1[NDST1];

__device__ int g_off0[NDST0 + 1];
__device__ int g_cur0[NDST0];
__device__ int g_csr0[E0];
__device__ int g_off1[NDST1 + 1];
__device__ int g_cur1[NDST1];
__device__ int g_csr1[E1];

// ---------------- degree histogram (counts zeroed by memsetAsync) ----------------
__global__ void k_hist(const int* __restrict__ s0, const int* __restrict__ d0,
                       const int* __restrict__ s1, const int* __restrict__ d1) {
    int i = blockIdx.x * blockDim.x + threadIdx.x;
    if (i < E0) {
        atomicAdd(&g_cnt[OFF_S0 + s0[i]], 1);
        atomicAdd(&g_cnt[OFF_D0 + d0[i]], 1);
    }
    if (i < E1) {
        atomicAdd(&g_cnt[OFF_S1 + s1[i]], 1);
        atomicAdd(&g_cnt[OFF_D1 + d1[i]], 1);
    }
}

// ---------------- scan (blocks 0,1) + norms (blocks 2+) ----------------
__global__ void __launch_bounds__(1024) k_prep() {
    int bid = blockIdx.x;
    if (bid < 2) {
        const int* cnt; int* off; int* cur; int n;
        if (bid == 0) { cnt = g_cnt + OFF_D0; off = g_off0; cur = g_cur0; n = NDST0; }
        else          { cnt = g_cnt + OFF_D1; off = g_off1; cur = g_cur1; n = NDST1; }
        int t = threadIdx.x;
        int per = (n + 1023) >> 10;
        int base = t * per;
        int s = 0;
        for (int i = 0; i < per; i++)
            if (base + i < n) s += cnt[base + i];
        int lane = t & 31, wid = t >> 5;
        int v = s;
        #pragma unroll
        for (int d = 1; d < 32; d <<= 1) {
            int x = __shfl_up_sync(~0u, v, d);
            if (lane >= d) v += x;
        }
        __shared__ int wsum[32];
        if (lane == 31) wsum[wid] = v;
        __syncthreads();
        if (wid == 0) {
            int wv = wsum[lane];
            #pragma unroll
            for (int d = 1; d < 32; d <<= 1) {
                int x = __shfl_up_sync(~0u, wv, d);
                if (lane >= d) wv += x;
            }
            wsum[lane] = wv;
        }
        __syncthreads();
        int run = v - s + (wid ? wsum[wid - 1] : 0);
        for (int i = 0; i < per; i++) {
            int idx = base + i;
            if (idx < n) { off[idx] = run; cur[idx] = run; run += cnt[idx]; }
        }
        if (t == 1023) off[n] = run;
    } else {
        int i = (bid - 2) * 1024 + threadIdx.x;
        if (i < NSRC0) g_ns0[i] = rsqrtf((float)max(g_cnt[OFF_S0 + i], 1));
        if (i < NDST0) {
            g_nd0[i] = rsqrtf((float)max(g_cnt[OFF_D0 + i], 1));
            g_ns1[i] = rsqrtf((float)max(g_cnt[OFF_S1 + i], 1));
        }
        if (i < NDST1) g_nd1[i] = rsqrtf((float)max(g_cnt[OFF_D1 + i], 1));
    }
}

__global__ void k_fill(const int* __restrict__ s0, const int* __restrict__ d0,
                       const int* __restrict__ s1, const int* __restrict__ d1) {
    int i = blockIdx.x * blockDim.x + threadIdx.x;
    if (i < E0) { int p = atomicAdd(&g_cur0[d0[i]], 1); g_csr0[p] = s0[i]; }
    if (i < E1) { int p = atomicAdd(&g_cur1[d1[i]], 1); g_csr1[p] = s1[i]; }
}

// ---------------- input transpose -> fp16 X (swizzled smem, 16B stores) ----------------
__global__ void __launch_bounds__(256) k_transpose(const float* __restrict__ inf) {
    __shared__ float4 sm4[64 * 33];
    const float* sm = (const float*)sm4;
    int fi0 = blockIdx.y * 64;
    int n0  = blockIdx.x * 128;
    int tid = threadIdx.x;

    #pragma unroll
    for (int i = 0; i < 8; i++) {
        int idx = i * 256 + tid;
        int f = idx >> 5;
        int v = idx & 31;
        int n = n0 + v * 4;
        if (n < NSRC0) {
            float4 x = *(const float4*)(inf + (size_t)(fi0 + f) * NSRC0 + n);
            sm4[f * 33 + (v ^ (f >> 3))] = x;
        }
    }
    __syncthreads();

    int a  = fi0 >> 8;
    int h0 = (fi0 & 255) >> 1;
    #pragma unroll
    for (int i = 0; i < 4; i++) {
        int idx = i * 256 + tid;
        int ln = idx >> 3;          // node 0..127
        int rest = idx & 7;
        int c = rest >> 2;
        int q2 = rest & 3;          // covers 8 output halves
        int n = n0 + ln;
        if (n < NSRC0) {
            int lq = ln >> 2, el = ln & 3;
            float v[8];
            #pragma unroll
            for (int jj = 0; jj < 8; jj++) {
                int fp = (q2 * 8 + jj) * 2 + c;        // local feature
                int col = lq ^ (fp >> 3);
                v[jj] = sm[(fp * 33 + col) * 4 + el];
            }
            __half2 p0 = __floats2half2_rn(v[0], v[1]);
            __half2 p1 = __floats2half2_rn(v[2], v[3]);
            __half2 p2 = __floats2half2_rn(v[4], v[5]);
            __half2 p3 = __floats2half2_rn(v[6], v[7]);
            uint4 pk = make_uint4(*(unsigned*)&p0, *(unsigned*)&p1,
                                  *(unsigned*)&p2, *(unsigned*)&p3);
            *(uint4*)(g_Xh + (size_t)n * FEAT + a * 256 + c * 128 + h0 + q2 * 8) = pk;
        }
    }
}

// ---------------- layer-0 aggregation: warp per dst, fp16 rows, fp32 accum, fp16 out ----------------
__global__ void k_agg_h(const int* __restrict__ off, const int* __restrict__ csr,
                        const __half* __restrict__ feat, const float* __restrict__ ns,
                        __half* __restrict__ out, int ndst) {
    int w = (blockIdx.x * blockDim.x + threadIdx.x) >> 5;
    int lane = threadIdx.x & 31;
    if (w >= ndst) return;
    int beg = off[w], end = off[w + 1];
    float acc[16];
    #pragma unroll
    for (int i = 0; i < 16; i++) acc[i] = 0.f;

    const uint4* base = (const uint4*)feat + lane;
    int e = beg;
    for (; e + 1 < end; e += 2) {
        int sA = csr[e], sB = csr[e + 1];
        float wA = ns[sA], wB = ns[sB];
        const uint4* pA = base + (size_t)sA * 64;
        const uint4* pB = base + (size_t)sB * 64;
        uint4 qa0 = pA[0], qa1 = pA[32];
        uint4 qb0 = pB[0], qb1 = pB[32];
        const __half2* ha0 = (const __half2*)&qa0;
        const __half2* ha1 = (const __half2*)&qa1;
        const __half2* hb0 = (const __half2*)&qb0;
        const __half2* hb1 = (const __half2*)&qb1;
        #pragma unroll
        for (int j = 0; j < 4; j++) {
            float2 va = __half22float2(ha0[j]);
            float2 vb = __half22float2(hb0[j]);
            acc[2 * j]     += wA * va.x + wB * vb.x;
            acc[2 * j + 1] += wA * va.y + wB * vb.y;
            float2 wa = __half22float2(ha1[j]);
            float2 wb = __half22float2(hb1[j]);
            acc[8 + 2 * j]     += wA * wa.x + wB * wb.x;
            acc[8 + 2 * j + 1] += wA * wa.y + wB * wb.y;
        }
    }
    if (e < end) {
        int sA = csr[e];
        float wA = ns[sA];
        const uint4* pA = base + (size_t)sA * 64;
        uint4 qa0 = pA[0], qa1 = pA[32];
        const __half2* ha0 = (const __half2*)&qa0;
        const __half2* ha1 = (const __half2*)&qa1;
        #pragma unroll
        for (int j = 0; j < 4; j++) {
            float2 va = __half22float2(ha0[j]);
            acc[2 * j]     += wA * va.x;
            acc[2 * j + 1] += wA * va.y;
            float2 wa = __half22float2(ha1[j]);
            acc[8 + 2 * j]     += wA * wa.x;
            acc[8 + 2 * j + 1] += wA * wa.y;
        }
    }
    __half2 o0 = __floats2half2_rn(acc[0], acc[1]);
    __half2 o1 = __floats2half2_rn(acc[2], acc[3]);
    __half2 o2 = __floats2half2_rn(acc[4], acc[5]);
    __half2 o3 = __floats2half2_rn(acc[6], acc[7]);
    __half2 o4 = __floats2half2_rn(acc[8], acc[9]);
    __half2 o5 = __floats2half2_rn(acc[10], acc[11]);
    __half2 o6 = __floats2half2_rn(acc[12], acc[13]);
    __half2 o7 = __floats2half2_rn(acc[14], acc[15]);
    __half* orow = out + (size_t)w * FEAT;
    *(uint4*)(orow + lane * 8) =
        make_uint4(*(unsigned*)&o0, *(unsigned*)&o1, *(unsigned*)&o2, *(unsigned*)&o3);
    *(uint4*)(orow + 256 + lane * 8) =
        make_uint4(*(unsigned*)&o4, *(unsigned*)&o5, *(unsigned*)&o6, *(unsigned*)&o7);
}

// ---------------- layer-0 HMMA GEMM: persistent, cp.async A tiles, fp16 out ----------------
#define PAH 136
__device__ __forceinline__ void issue_tile_cp_h(__half* dst, const __half* __restrict__ src, int tid) {
    #pragma unroll 8
    for (int i = tid; i < 2048; i += 256) {
        int r = i >> 4, k8 = i & 15;
        unsigned sa = (unsigned)__cvta_generic_to_shared(dst + r * PAH + k8 * 8);
        asm volatile("cp.async.cg.shared.global [%0], [%1], 16;"
                     :: "r"(sa), "l"(src + r * Hd + k8 * 8));
    }
}

__device__ __forceinline__ void load_W_fp16(__half* Ws, const float* __restrict__ Wm,
                                            float* bs, const float* __restrict__ bias, int tid) {
    #pragma unroll 4
    for (int i = tid; i < 4096; i += 256) {
        int k = i >> 5, c4 = i & 31;
        float4 v = *((const float4*)(Wm + k * Hd) + c4);
        __half2 h0 = __floats2half2_rn(v.x, v.y);
        __half2 h1 = __floats2half2_rn(v.z, v.w);
        *(uint2*)(Ws + k * PAH + c4 * 4) = make_uint2(*(unsigned*)&h0, *(unsigned*)&h1);
    }
    if (tid < 128) bs[tid] = bias[tid];
}

__global__ void __launch_bounds__(256)
k_gemm_h(const __half* __restrict__ A, const float* __restrict__ Wm,
         const float* __restrict__ bias, const float* __restrict__ nd,
         const float* __restrict__ s2, __half* __restrict__ Crow, int ntiles) {
    extern __shared__ __align__(16) char smem_raw[];
    __half* bufs[2] = { (__half*)smem_raw, (__half*)smem_raw + 128 * PAH };
    __half* Ws = (__half*)smem_raw + 2 * 128 * PAH;
    float* bs = (float*)((__half*)smem_raw + 3 * 128 * PAH);
    int tid = threadIdx.x;
    int lane = tid & 31;
    int wid = tid >> 5;
    int wr = wid >> 1;
    int wc = wid & 1;

    load_W_fp16(Ws, Wm, bs, bias, tid);

    int t0 = blockIdx.x;
    if (t0 < ntiles) issue_tile_cp_h(bufs[0], A + (size_t)t0 * 128 * Hd, tid);
    asm volatile("cp.async.commit_group;" ::: "memory");

    int pb = 0;
    for (int t = t0; t < ntiles; t += gridDim.x) {
        asm volatile("cp.async.wait_group 0;" ::: "memory");
        __syncthreads();
        __half* Ash = bufs[pb];
        int tn = t + gridDim.x;
        if (tn < ntiles) issue_tile_cp_h(bufs[pb ^ 1], A + (size_t)tn * 128 * Hd, tid);
        asm volatile("cp.async.commit_group;" ::: "memory");
        pb ^= 1;

        float acc[2][8][4];
        #pragma unroll
        for (int rt = 0; rt < 2; rt++)
            #pragma unroll
            for (int j = 0; j < 8; j++)
                #pragma unroll
                for (int q = 0; q < 4; q++) acc[rt][j][q] = 0.f;

        #pragma unroll
        for (int k0 = 0; k0 < 8; k0++) {
            unsigned a[2][4];
            #pragma unroll
            for (int rt = 0; rt < 2; rt++) {
                int row = wr * 32 + rt * 16 + (lane & 15);
                unsigned ad = (unsigned)__cvta_generic_to_shared(
                    Ash + row * PAH + k0 * 16 + (lane >> 4) * 8);
                asm volatile("ldmatrix.sync.aligned.m8n8.x4.shared.b16 {%0,%1,%2,%3}, [%4];"
                             : "=r"(a[rt][0]), "=r"(a[rt][1]), "=r"(a[rt][2]), "=r"(a[rt][3])
                             : "r"(ad));
            }
            unsigned bf[8][2];
            #pragma unroll
            for (int p = 0; p < 4; p++) {
                int krow = k0 * 16 + (lane & 15);
                int ncol = wc * 64 + p * 16 + (lane >> 4) * 8;
                unsigned ad = (unsigned)__cvta_generic_to_shared(Ws + krow * PAH + ncol);
                asm volatile("ldmatrix.sync.aligned.m8n8.x4.trans.shared.b16 {%0,%1,%2,%3}, [%4];"
                             : "=r"(bf[2 * p][0]), "=r"(bf[2 * p][1]),
                               "=r"(bf[2 * p + 1][0]), "=r"(bf[2 * p + 1][1])
                             : "r"(ad));
            }
            #pragma unroll
            for (int rt = 0; rt < 2; rt++)
                #pragma unroll
                for (int j = 0; j < 8; j++)
                    asm volatile("mma.sync.aligned.m16n8k16.row.col.f32.f16.f16.f32 "
                                 "{%0,%1,%2,%3}, {%4,%5,%6,%7}, {%8,%9}, {%0,%1,%2,%3};"
                                 : "+f"(acc[rt][j][0]), "+f"(acc[rt][j][1]),
                                   "+f"(acc[rt][j][2]), "+f"(acc[rt][j][3])
                                 : "r"(a[rt][0]), "r"(a[rt][1]), "r"(a[rt][2]), "r"(a[rt][3]),
                                   "r"(bf[j][0]), "r"(bf[j][1]));
        }

        int node0 = t * 32;
        size_t row0 = (size_t)t * 128;
        int gid = lane >> 2, tig = lane & 3;

        #pragma unroll
        for (int rt = 0; rt < 2; rt++)
            #pragma unroll
            for (int hh = 0; hh < 2; hh++) {
                int rl = wr * 32 + rt * 16 + gid + hh * 8;
                int node = node0 + (rl >> 2);
                float sc = nd[node];
                float s2v = s2[node];
                #pragma unroll
                for (int j = 0; j < 8; j++) {
                    int col = wc * 64 + j * 8 + tig * 2;
                    float o0 = fmaxf(acc[rt][j][hh * 2 + 0] * sc + bs[col], 0.f) * s2v;
                    float o1 = fmaxf(acc[rt][j][hh * 2 + 1] * sc + bs[col + 1], 0.f) * s2v;
                    __half2 hv = __floats2half2_rn(o0, o1);
                    *(__half2*)(Crow + (row0 + rl) * Hd + col) = hv;
                }
            }
    }
}

// ---------------- fused layer 1: gather(h0) -> HMMA -> transposed fp32 out ----------------
// 128 blocks, one 32-node tile each. smem: Ash | Ws (fp16) then Fsh overlay; bias after.
__global__ void __launch_bounds__(256)
k_l1_fused(const int* __restrict__ off, const int* __restrict__ csr,
           const __half* __restrict__ feat, const float* __restrict__ Wm,
           const float* __restrict__ bias, const float* __restrict__ nd,
           float* __restrict__ Ctr) {
    extern __shared__ __align__(16) char smem_raw[];
    __half* Ash = (__half*)smem_raw;
    __half* Ws  = (__half*)smem_raw + 128 * PAH;
    float* bs   = (float*)((__half*)smem_raw + 2 * 128 * PAH);
    int tid = threadIdx.x;
    int lane = tid & 31;
    int wid = tid >> 5;
    int node0 = blockIdx.x * 32;

    load_W_fp16(Ws, Wm, bs, bias, tid);

    // gather: warp wid aggregates local nodes wid*4..+3 into Ash
    const uint4* base = (const uint4*)feat + lane;
    int g0 = lane >> 4;            // feature group within [0,256)
    int cc = (lane & 15) * 8;      // column within 128
    #pragma unroll
    for (int t2 = 0; t2 < 4; t2++) {
        int ln = wid * 4 + t2;
        int node = node0 + ln;
        int beg = off[node], end = off[node + 1];
        float acc[16];
        #pragma unroll
        for (int i = 0; i < 16; i++) acc[i] = 0.f;
        int e = beg;
        for (; e + 1 < end; e += 2) {
            int sA = csr[e], sB = csr[e + 1];
            const uint4* pA = base + (size_t)sA * 64;
            const uint4* pB = base + (size_t)sB * 64;
            uint4 qa0 = pA[0], qa1 = pA[32];
            uint4 qb0 = pB[0], qb1 = pB[32];
            const __half2* ha0 = (const __half2*)&qa0;
            const __half2* ha1 = (const __half2*)&qa1;
            const __half2* hb0 = (const __half2*)&qb0;
            const __half2* hb1 = (const __half2*)&qb1;
            #pragma unroll
            for (int j = 0; j < 4; j++) {
                float2 va = __half22float2(ha0[j]);
                float2 vb = __half22float2(hb0[j]);
                acc[2 * j]     += va.x + vb.x;
                acc[2 * j + 1] += va.y + vb.y;
                float2 wa = __half22float2(ha1[j]);
                float2 wb = __half22float2(hb1[j]);
                acc[8 + 2 * j]     += wa.x + wb.x;
                acc[8 + 2 * j + 1] += wa.y + wb.y;
            }
        }
        if (e < end) {
            const uint4* pA = base + (size_t)csr[e] * 64;
            uint4 qa0 = pA[0], qa1 = pA[32];
            const __half2* ha0 = (const __half2*)&qa0;
            const __half2* ha1 = (const __half2*)&qa1;
            #pragma unroll
            for (int j = 0; j < 4; j++) {
                float2 va = __half22float2(ha0[j]);
                acc[2 * j]     += va.x;
                acc[2 * j + 1] += va.y;
                float2 wa = __half22float2(ha1[j]);
                acc[8 + 2 * j]     += wa.x;
                acc[8 + 2 * j + 1] += wa.y;
            }
        }
        __half2 o0 = __floats2half2_rn(acc[0], acc[1]);
        __half2 o1 = __floats2half2_rn(acc[2], acc[3]);
        __half2 o2 = __floats2half2_rn(acc[4], acc[5]);
        __half2 o3 = __floats2half2_rn(acc[6], acc[7]);
        __half2 o4 = __floats2half2_rn(acc[8], acc[9]);
        __half2 o5 = __floats2half2_rn(acc[10], acc[11]);
        __half2 o6 = __floats2half2_rn(acc[12], acc[13]);
        __half2 o7 = __floats2half2_rn(acc[14], acc[15]);
        // features [lane*8..+7] -> row ln*4 + g0, cols cc..cc+7
        *(uint4*)(Ash + (ln * 4 + g0) * PAH + cc) =
            make_uint4(*(unsigned*)&o0, *(unsigned*)&o1, *(unsigned*)&o2, *(unsigned*)&o3);
        *(uint4*)(Ash + (ln * 4 + 2 + g0) * PAH + cc) =
            make_uint4(*(unsigned*)&o4, *(unsigned*)&o5, *(unsigned*)&o6, *(unsigned*)&o7);
    }
    __syncthreads();

    // HMMA mainloop (single tile)
    int wr = wid >> 1;
    int wc = wid & 1;
    float acc[2][8][4];
    #pragma unroll
    for (int rt = 0; rt < 2; rt++)
        #pragma unroll
        for (int j = 0; j < 8; j++)
            #pragma unroll
            for (int q = 0; q < 4; q++) acc[rt][j][q] = 0.f;

    #pragma unroll
    for (int k0 = 0; k0 < 8; k0++) {
        unsigned a[2][4];
        #pragma unroll
        for (int rt = 0; rt < 2; rt++) {
            int row = wr * 32 + rt * 16 + (lane & 15);
            unsigned ad = (unsigned)__cvta_generic_to_shared(
                Ash + row * PAH + k0 * 16 + (lane >> 4) * 8);
            asm volatile("ldmatrix.sync.aligned.m8n8.x4.shared.b16 {%0,%1,%2,%3}, [%4];"
                         : "=r"(a[rt][0]), "=r"(a[rt][1]), "=r"(a[rt][2]), "=r"(a[rt][3])
                         : "r"(ad));
        }
        unsigned bf[8][2];
        #pragma unroll
        for (int p = 0; p < 4; p++) {
            int krow = k0 * 16 + (lane & 15);
            int ncol = wc * 64 + p * 16 + (lane >> 4) * 8;
            unsigned ad = (unsigned)__cvta_generic_to_shared(Ws + krow * PAH + ncol);
            asm volatile("ldmatrix.sync.aligned.m8n8.x4.trans.shared.b16 {%0,%1,%2,%3}, [%4];"
                         : "=r"(bf[2 * p][0]), "=r"(bf[2 * p][1]),
                           "=r"(bf[2 * p + 1][0]), "=r"(bf[2 * p + 1][1])
                         : "r"(ad));
        }
        #pragma unroll
        for (int rt = 0; rt < 2; rt++)
            #pragma unroll
            for (int j = 0; j < 8; j++)
                asm volatile("mma.sync.aligned.m16n8k16.row.col.f32.f16.f16.f32 "
                             "{%0,%1,%2,%3}, {%4,%5,%6,%7}, {%8,%9}, {%0,%1,%2,%3};"
                             : "+f"(acc[rt][j][0]), "+f"(acc[rt][j][1]),
                               "+f"(acc[rt][j][2]), "+f"(acc[rt][j][3])
                             : "r"(a[rt][0]), "r"(a[rt][1]), "r"(a[rt][2]), "r"(a[rt][3]),
                               "r"(bf[j][0]), "r"(bf[j][1]));
    }

    // transposed fp32 epilogue; Fsh overlays Ash+Ws (67.6KB < 69.6KB); bs beyond, safe
    __syncthreads();
    float* Fsh = (float*)smem_raw;   // [512][33]
    int gid = lane >> 2, tig = lane & 3;
    #pragma unroll
    for (int rt = 0; rt < 2; rt++)
        #pragma unroll
        for (int hh = 0; hh < 2; hh++) {
            int rl = wr * 32 + rt * 16 + gid + hh * 8;
            int node = node0 + (rl >> 2);
            int ln = rl >> 2, g = rl & 3;
            float sc = nd[node];
            #pragma unroll
            for (int j = 0; j < 8; j++) {
                int col = wc * 64 + j * 8 + tig * 2;
                float o0 = fmaxf(acc[rt][j][hh * 2 + 0] * sc + bs[col], 0.f);
                float o1 = fmaxf(acc[rt][j][hh * 2 + 1] * sc + bs[col + 1], 0.f);
                int f0 = g * 128 + col;
                Fsh[(f0 + 0) * 33 + ln] = o0;
                Fsh[(f0 + 1) * 33 + ln] = o1;
            }
        }
    __syncthreads();
    for (int f = tid >> 5; f < FEAT; f += 8) {
        int g = f >> 7, h = f & 127;
        int a2 = g >> 1, c2 = g & 1;
        int fo = (a2 * 128 + h) * 2 + c2;
        Ctr[(size_t)fo * NDST1 + node0 + lane] = Fsh[f * 33 + lane];
    }
}

// ---------------- launcher ----------------
extern "C" void kernel_launch(void* const* d_in, const int* in_sizes, int n_in,
                              void* d_out, int out_size) {
    const float* in_feat = (const float*)d_in[0];
    const float* W       = (const float*)d_in[1];
    const float* b       = (const float*)d_in[2];
    const int* e0s = (const int*)d_in[3];
    const int* e0d = (const int*)d_in[4];
    const int* e1s = (const int*)d_in[5];
    const int* e1d = (const int*)d_in[6];
    float* out = (float*)d_out;

    void *pXh, *pagg0, *ph0, *pcnt;
    void *poff0, *pcsr0, *poff1, *pcsr1;
    void *pns0, *pnd0, *pns1, *pnd1;
    cudaGetSymbolAddress(&pXh, g_Xh);
    cudaGetSymbolAddress(&pagg0, g_agg0);
    cudaGetSymbolAddress(&ph0, g_h0);
    cudaGetSymbolAddress(&pcnt, g_cnt);
    cudaGetSymbolAddress(&poff0, g_off0);
    cudaGetSymbolAddress(&pcsr0, g_csr0);
    cudaGetSymbolAddress(&poff1, g_off1);
    cudaGetSymbolAddress(&pcsr1, g_csr1);
    cudaGetSymbolAddress(&pns0, g_ns0);
    cudaGetSymbolAddress(&pnd0, g_nd0);
    cudaGetSymbolAddress(&pns1, g_ns1);
    cudaGetSymbolAddress(&pnd1, g_nd1);

    int smem_g = 3 * 128 * PAH * 2 + 512;     // gemm0: 2 A bufs + W + bias
    int smem_f = 2 * 128 * PAH * 2 + 512;     // fused l1: A + W + bias
    cudaFuncSetAttribute(k_gemm_h, cudaFuncAttributeMaxDynamicSharedMemorySize, smem_g);
    cudaFuncSetAttribute(k_l1_fused, cudaFuncAttributeMaxDynamicSharedMemorySize, smem_f);

    static cudaStream_t s2 = nullptr;
    static cudaEvent_t evFork = nullptr, evT = nullptr;
    if (!s2) {
        cudaStreamCreateWithFlags(&s2, cudaStreamNonBlocking);
        cudaEventCreateWithFlags(&evFork, cudaEventDisableTiming);
        cudaEventCreateWithFlags(&evT, cudaEventDisableTiming);
    }

    // main stream: graph prep chain
    cudaEventRecord(evFork, 0);
    cudaMemsetAsync(pcnt, 0, CNT_TOTAL * sizeof(int));
    k_hist<<<(E0 + 255) / 256, 256>>>(e0s, e0d, e1s, e1d);
    k_prep<<<2 + (NSRC0 + 1023) / 1024, 1024>>>();
    k_fill<<<(E0 + 255) / 256, 256>>>(e0s, e0d, e1s, e1d);

    // transpose on s2 (waits only on capture start)
    cudaStreamWaitEvent(s2, evFork, 0);
    {
        dim3 gr((NSRC0 + 127) / 128, FEAT / 64);
        k_transpose<<<gr, 256, 0, s2>>>(in_feat);
    }
    cudaEventRecord(evT, s2);
    cudaStreamWaitEvent(0, evT, 0);

    // layer 0: fp16 agg(*ns0[src]) -> HMMA GEMM(*nd0 + b, relu, *ns1) -> fp16 h0
    k_agg_h<<<(NDST0 + 7) / 8, 256>>>((const int*)poff0, (const int*)pcsr0,
                                      (const __half*)pXh, (const float*)pns0,
                                      (__half*)pagg0, NDST0);
    k_gemm_h<<<296, 256, smem_g>>>((const __half*)pagg0, W, b,
                                   (const float*)pnd0, (const float*)pns1,
                                   (__half*)ph0, NDST0 * 4 / 128);

    // layer 1 fused: gather(h0) -> HMMA(*nd1 + b, relu) -> transposed fp32 out
    k_l1_fused<<<NDST1 / 32, 256, smem_f>>>((const int*)poff1, (const int*)pcsr1,
                                            (const __half*)ph0, W, b,
                                            (const float*)pnd1, out);

    (void)in_sizes; (void)n_in; (void)out_size;
}